// round 8
// baseline (speedup 1.0000x reference)
#include <cuda_runtime.h>
#include <mma.h>
#include <math.h>

using namespace nvcuda;

#define BB 64
#define LL 50
#define HH 1024
#define VV 50257

// ------------------------ scratch ------------------------
__device__ __align__(16) float g_x[BB * HH];
__device__ __align__(16) float g_q[BB * HH];
__device__ __align__(16) float g_scores[BB * LL];
__device__ __align__(16) float g_attn[BB * LL];
__device__ __align__(16) float g_wenc[BB * 2 * HH];
__device__ __align__(16) float g_hnext[BB * HH];
__device__ __align__(16) float g_lse[BB * 8 * 2];
// split-K partials (8 splits each)
__device__ __align__(16) float g_partq[8 * BB * HH];
__device__ __align__(16) float g_partqk[8 * BB * 2 * HH];
__device__ __align__(16) float g_partc[8 * BB * HH];
__device__ __align__(16) float g_partg[8 * BB * 4 * HH];

// ------------------------ cp.async helpers ------------------------
__device__ __forceinline__ unsigned smem_u32(const void* p) {
    return (unsigned)__cvta_generic_to_shared(p);
}
__device__ __forceinline__ void cp16(unsigned dst, const void* src) {
    asm volatile("cp.async.cg.shared.global [%0], [%1], 16;\n" :: "r"(dst), "l"(src));
}
__device__ __forceinline__ void cp4(unsigned dst, const void* src, int sz) {
    asm volatile("cp.async.ca.shared.global [%0], [%1], 4, %2;\n" :: "r"(dst), "l"(src), "r"(sz));
}
__device__ __forceinline__ void cp_commit() { asm volatile("cp.async.commit_group;\n"); }
template <int N> __device__ __forceinline__ void cp_wait() {
    asm volatile("cp.async.wait_group %0;\n" :: "n"(N));
}

// ------------------------ embedding gather ------------------------
__global__ void __launch_bounds__(256) k_gather(const int* __restrict__ idx,
                                                const float* __restrict__ emb) {
    int b = blockIdx.x;
    const float4* src = (const float4*)(emb + (size_t)idx[b] * HH);
    float4* dst = (float4*)(g_x + b * HH);
    if (threadIdx.x < HH / 4) dst[threadIdx.x] = src[threadIdx.x];
}

// ------------------------ q = sum(8 parts) + bias ------------------------
__global__ void __launch_bounds__(256) k_qbias(const float* __restrict__ query_b) {
    int b = blockIdx.x;
    int j = blockIdx.y * 256 + threadIdx.x;
    float s = query_b[j];
#pragma unroll
    for (int p = 0; p < 8; p++) s += g_partq[p * BB * HH + b * HH + j];
    g_q[b * HH + j] = s;
}

// ------------------------ pipelined M=64 tf32 GEMM with split-K ------------------------
// C[64,N] = [A1 | A2] @ [B1 ; B2].  !B_NK: B row-major [K,N]; B_NK: B is [N,K] (B^T mult).
// gridDim.y = KS splits; split ky writes partials to C + ky*64*ldc.
// B fills: 16B cp.async when ldb % 4 == 0, else coalesced 4B cp.async (odd-ldb out_w).
// Single barrier per chunk: wait -> sync -> issue(t+S-1) -> compute.
template <int BN, int S, bool B_NK>
__global__ void __launch_bounds__(256) gemm_pipe(
    const float* __restrict__ A1, const float* __restrict__ A2, int K1, int Ktot,
    const float* __restrict__ B1, const float* __restrict__ B2, int ldb1, int ldb2,
    float* __restrict__ C, int ldc, int N) {
    constexpr int BK  = 16;
    constexpr int AP  = 20;
    constexpr int BPL = BN + 4;     // KN row stride
    constexpr int BNS = 20;         // NK row stride
    constexpr int BSTG = B_NK ? (BN * BNS) : (BK * BPL);
    constexpr int TN = BN / 32;

    extern __shared__ char dsm[];
    float* sA = (float*)dsm;
    float* sB = (float*)(dsm + (size_t)S * 64 * AP * 4);

    const int tid = threadIdx.x, w = tid >> 5;
    const int wm = w & 3, wn = w >> 2;
    const int n0 = blockIdx.x * BN;
    const int Tall = Ktot / BK;
    const int Tper = Tall / gridDim.y;
    const int t0 = blockIdx.y * Tper;
    const bool fullN = (n0 + BN) <= N;
    const bool bAligned = (((ldb1 | ldb2) & 3) == 0);
    C += (size_t)blockIdx.y * 64 * ldc;

    auto issue = [&](int t) {
        int k0 = t * BK;
        const float* Aseg; const float* Bseg; int lda, ldb, kk;
        if (k0 < K1) { Aseg = A1; Bseg = B1; lda = K1;        ldb = ldb1; kk = k0; }
        else         { Aseg = A2; Bseg = B2; lda = Ktot - K1; ldb = ldb2; kk = k0 - K1; }
        int buf = (t - t0) % S;
        // A: 64x16 floats = 256 float4, one per thread (16B-aligned sources)
        int ar = tid >> 2, av = (tid & 3) * 4;
        cp16(smem_u32(&sA[buf * 64 * AP + ar * AP + av]), Aseg + (size_t)ar * lda + kk + av);
        float* sBb = &sB[buf * BSTG];
        if (!B_NK) {
            if (bAligned) {
                constexpr int NV = BN / 4;
                constexpr int TOT = BK * NV;
#pragma unroll
                for (int i = tid; i < TOT; i += 256) {
                    int r = i / NV, c = (i % NV) * 4;
                    cp16(smem_u32(&sBb[r * BPL + c]), Bseg + (size_t)(kk + r) * ldb + n0 + c);
                }
            } else {
                // odd ldb (out_w): coalesced 4B cp.async, zfill out-of-range
                constexpr int TOT = BK * BN;
#pragma unroll
                for (int i = tid; i < TOT; i += 256) {
                    int r = i / BN, c = i % BN;
                    int n = n0 + c;
                    int ok = (fullN || n < N);
                    const float* src = Bseg + (size_t)(kk + r) * ldb + (ok ? n : 0);
                    cp4(smem_u32(&sBb[r * BPL + c]), src, ok ? 4 : 0);
                }
            }
        } else {
            constexpr int TOT = BN * 4;                // BN rows x 4 float4
#pragma unroll
            for (int i = tid; i < TOT; i += 256) {
                int r = i >> 2, c = (i & 3) * 4;
                int n = n0 + r;
                cp16(smem_u32(&sBb[r * BNS + c]), Bseg + (size_t)n * ldb + kk + c);
            }
        }
    };

    wmma::fragment<wmma::matrix_a, 16, 16, 8, wmma::precision::tf32, wmma::row_major> fa;
    wmma::fragment<wmma::accumulator, 16, 16, 8, float> fc[TN];
#pragma unroll
    for (int t = 0; t < TN; t++) wmma::fill_fragment(fc[t], 0.f);

#pragma unroll
    for (int p = 0; p < S - 1; p++) { if (p < Tper) issue(t0 + p); cp_commit(); }

    for (int t = t0; t < t0 + Tper; t++) {
        cp_wait<S - 2>();
        __syncthreads();                    // all warps done with buf (t-1)%S; chunk t resident
        if (t + S - 1 < t0 + Tper) issue(t + S - 1);
        cp_commit();
        int buf = (t - t0) % S;
        float* sAb = &sA[buf * 64 * AP];
        float* sBb = &sB[buf * BSTG];
#pragma unroll
        for (int ks = 0; ks < 2; ks++) {
            wmma::load_matrix_sync(fa, &sAb[wm * 16 * AP + ks * 8], AP);
#pragma unroll
            for (int i = 0; i < fa.num_elements; i++) fa.x[i] = wmma::__float_to_tf32(fa.x[i]);
#pragma unroll
            for (int tt = 0; tt < TN; tt++) {
                int ns = wn * (BN / 2) + tt * 16;
                if (!B_NK) {
                    wmma::fragment<wmma::matrix_b, 16, 16, 8, wmma::precision::tf32, wmma::row_major> fb;
                    wmma::load_matrix_sync(fb, &sBb[ks * 8 * BPL + ns], BPL);
#pragma unroll
                    for (int i = 0; i < fb.num_elements; i++) fb.x[i] = wmma::__float_to_tf32(fb.x[i]);
                    wmma::mma_sync(fc[tt], fa, fb, fc[tt]);
                } else {
                    wmma::fragment<wmma::matrix_b, 16, 16, 8, wmma::precision::tf32, wmma::col_major> fb;
                    wmma::load_matrix_sync(fb, &sBb[ns * BNS + ks * 8], BNS);
#pragma unroll
                    for (int i = 0; i < fb.num_elements; i++) fb.x[i] = wmma::__float_to_tf32(fb.x[i]);
                    wmma::mma_sync(fc[tt], fa, fb, fc[tt]);
                }
            }
        }
    }

    __syncthreads();
    const bool ldc_ok = (ldc & 3) == 0;
    if (ldc_ok && fullN) {
#pragma unroll
        for (int tt = 0; tt < TN; tt++) {
            int nc = n0 + wn * (BN / 2) + tt * 16;
            wmma::store_matrix_sync(&C[(size_t)(wm * 16) * ldc + nc], fc[tt], ldc, wmma::mem_row_major);
        }
    } else {
        constexpr int CP = BN + 4;
        float* sC = sA;
#pragma unroll
        for (int tt = 0; tt < TN; tt++) {
            int ns = wn * (BN / 2) + tt * 16;
            wmma::store_matrix_sync(&sC[(size_t)(wm * 16) * CP + ns], fc[tt], CP, wmma::mem_row_major);
        }
        __syncthreads();
        for (int i = tid; i < 64 * BN; i += 256) {
            int r = i / BN, c = i % BN;
            int n = n0 + c;
            if (n < N) C[(size_t)r * ldc + n] = sC[r * CP + c];
        }
    }
}

// ------------------------ attention scores ------------------------
__global__ void __launch_bounds__(256) k_scores(const float* __restrict__ enc) {
    int b = blockIdx.x;
    int tid = threadIdx.x, w = tid >> 5, lane = tid & 31;
    __shared__ __align__(16) float sq[2 * HH];
    for (int j = tid; j < 2 * HH; j += 256) {
        float s = 0.f;
#pragma unroll
        for (int p = 0; p < 8; p++) s += g_partqk[p * BB * 2 * HH + b * 2 * HH + j];
        sq[j] = s;
    }
    __syncthreads();

    for (int ll = w; ll < 10; ll += 8) {
        int l = blockIdx.y * 10 + ll;
        const float* e = enc + ((size_t)b * LL + l) * 2 * HH;
        float acc = 0.f;
        for (int j = lane * 4; j < 2 * HH; j += 128) {
            float4 ev = *(const float4*)(e + j);
            float4 qv = *(const float4*)(sq + j);
            acc += ev.x * qv.x + ev.y * qv.y + ev.z * qv.z + ev.w * qv.w;
        }
#pragma unroll
        for (int o = 16; o > 0; o >>= 1) acc += __shfl_xor_sync(0xffffffffu, acc, o);
        if (lane == 0) g_scores[b * LL + l] = acc * (1.f / HH);
    }
}

// ------------------------ softmax over L=50 ------------------------
__global__ void __launch_bounds__(32) k_softmax(float* __restrict__ out_attn) {
    int b = blockIdx.x, t = threadIdx.x;
    float v0 = (t < LL) ? g_scores[b * LL + t] : -1e30f;
    float v1 = (t + 32 < LL) ? g_scores[b * LL + t + 32] : -1e30f;
    float m = fmaxf(v0, v1);
#pragma unroll
    for (int o = 16; o > 0; o >>= 1) m = fmaxf(m, __shfl_xor_sync(0xffffffffu, m, o));
    float e0 = (t < LL) ? expf(v0 - m) : 0.f;
    float e1 = (t + 32 < LL) ? expf(v1 - m) : 0.f;
    float s = e0 + e1;
#pragma unroll
    for (int o = 16; o > 0; o >>= 1) s += __shfl_xor_sync(0xffffffffu, s, o);
    float inv = 1.f / s;
    if (t < LL)      { g_attn[b * LL + t] = e0 * inv;      if (out_attn) out_attn[b * LL + t] = e0 * inv; }
    if (t + 32 < LL) { g_attn[b * LL + t + 32] = e1 * inv; if (out_attn) out_attn[b * LL + t + 32] = e1 * inv; }
}

// ------------------------ weighted encoder sum ------------------------
__global__ void __launch_bounds__(256) k_wenc(const float* __restrict__ enc) {
    int b = blockIdx.x;
    int j = blockIdx.y * 256 + threadIdx.x;
    __shared__ float at[LL];
    if (threadIdx.x < LL) at[threadIdx.x] = g_attn[b * LL + threadIdx.x];
    __syncthreads();
    const float* e = enc + (size_t)b * LL * 2 * HH + j;
    float acc = 0.f;
#pragma unroll 5
    for (int l = 0; l < LL; l++) acc += at[l] * e[(size_t)l * 2 * HH];
    g_wenc[b * 2 * HH + j] = acc;
}

// ------------------------ LSTM elementwise (sums 8 split-K parts, folds biases) ------------------------
__global__ void __launch_bounds__(256) k_lstm(const float* __restrict__ value_b,
                                              const float* __restrict__ b_x,
                                              const float* __restrict__ b_h,
                                              float* __restrict__ out_h) {
    int b = blockIdx.x;
    int h = blockIdx.y * 256 + threadIdx.x;
    float gf = b_x[h]          + b_h[h];
    float gi = b_x[HH + h]     + b_h[HH + h];
    float gc = b_x[2 * HH + h] + b_h[2 * HH + h];
    float go = b_x[3 * HH + h] + b_h[3 * HH + h];
#pragma unroll
    for (int p = 0; p < 8; p++) {
        const float* g = g_partg + (size_t)p * BB * 4 * HH + b * 4 * HH;
        gf += g[h]; gi += g[HH + h]; gc += g[2 * HH + h]; go += g[3 * HH + h];
    }
    float cp = value_b[h];
#pragma unroll
    for (int p = 0; p < 8; p++) cp += g_partc[p * BB * HH + b * HH + h];

    float f  = 1.f / (1.f + expf(-gf));
    float ig = 1.f / (1.f + expf(-gi));
    float cb = tanhf(gc);
    float o  = 1.f / (1.f + expf(-go));
    float c  = f * cp + ig * cb;
    float hn = o * tanhf(c);
    g_hnext[b * HH + h] = hn;
    if (out_h) out_h[b * HH + h] = hn;
}

// ------------------------ log-softmax: pass1 partial, pass2 apply ------------------------
#define LSM_CH 6283
__global__ void __launch_bounds__(256) k_lsm1(const float* __restrict__ logits,
                                              const float* __restrict__ out_b) {
    int b = blockIdx.x, c = blockIdx.y, tid = threadIdx.x;
    int start = c * LSM_CH, end = min(start + LSM_CH, VV);
    const float* row = logits + (size_t)b * VV;
    __shared__ float red[256];
    float m = -1e30f;
    for (int v = start + tid; v < end; v += 256) m = fmaxf(m, row[v] + out_b[v]);
    red[tid] = m; __syncthreads();
    for (int s = 128; s > 0; s >>= 1) { if (tid < s) red[tid] = fmaxf(red[tid], red[tid + s]); __syncthreads(); }
    m = red[0]; __syncthreads();
    float sum = 0.f;
    for (int v = start + tid; v < end; v += 256) sum += __expf(row[v] + out_b[v] - m);
    red[tid] = sum; __syncthreads();
    for (int s = 128; s > 0; s >>= 1) { if (tid < s) red[tid] += red[tid + s]; __syncthreads(); }
    if (tid == 0) { g_lse[(b * 8 + c) * 2] = m; g_lse[(b * 8 + c) * 2 + 1] = red[0]; }
}

__global__ void __launch_bounds__(256) k_lsm2(float* __restrict__ logits,
                                              const float* __restrict__ out_b) {
    int b = blockIdx.x, c = blockIdx.y, tid = threadIdx.x;
    float M = -1e30f;
#pragma unroll
    for (int i = 0; i < 8; i++) M = fmaxf(M, g_lse[(b * 8 + i) * 2]);
    float S = 0.f;
#pragma unroll
    for (int i = 0; i < 8; i++) S += g_lse[(b * 8 + i) * 2 + 1] * __expf(g_lse[(b * 8 + i) * 2] - M);
    float lse = M + logf(S);
    int start = c * LSM_CH, end = min(start + LSM_CH, VV);
    float* row = logits + (size_t)b * VV;
    for (int v = start + tid; v < end; v += 256) row[v] = row[v] + out_b[v] - lse;
}

// ------------------------ launch ------------------------
extern "C" void kernel_launch(void* const* d_in, const int* in_sizes, int n_in,
                              void* d_out, int out_size) {
    (void)in_sizes; (void)n_in;
    const int*   idx     = (const int*)  d_in[0];
    const float* h_prev  = (const float*)d_in[1];
    const float* enc     = (const float*)d_in[2];
    const float* emb     = (const float*)d_in[3];
    const float* w_x     = (const float*)d_in[4];
    const float* b_x     = (const float*)d_in[5];
    const float* w_h     = (const float*)d_in[6];
    const float* b_h     = (const float*)d_in[7];
    const float* key_w   = (const float*)d_in[8];
    const float* value_w = (const float*)d_in[10];
    const float* value_b = (const float*)d_in[11];
    const float* query_w = (const float*)d_in[12];
    const float* query_b = (const float*)d_in[13];
    const float* out_w   = (const float*)d_in[14];
    const float* out_b   = (const float*)d_in[15];
    // d_in[9] = key_b: dropped — softmax is shift-invariant in the constant q·key_b.

    float* out      = (float*)d_out;
    float* out_logp = out;
    float* out_h    = nullptr;
    float* out_attn = nullptr;
    long long need = (long long)BB * VV + (long long)BB * HH + (long long)BB * LL;
    if ((long long)out_size >= need) {
        out_h    = out + (size_t)BB * VV;
        out_attn = out_h + (size_t)BB * HH;
    }

    float *p_x, *p_q, *p_wenc, *p_hnext, *p_partq, *p_partqk, *p_partc, *p_partg;
    cudaGetSymbolAddress((void**)&p_x,      g_x);
    cudaGetSymbolAddress((void**)&p_q,      g_q);
    cudaGetSymbolAddress((void**)&p_wenc,   g_wenc);
    cudaGetSymbolAddress((void**)&p_hnext,  g_hnext);
    cudaGetSymbolAddress((void**)&p_partq,  g_partq);
    cudaGetSymbolAddress((void**)&p_partqk, g_partqk);
    cudaGetSymbolAddress((void**)&p_partc,  g_partc);
    cudaGetSymbolAddress((void**)&p_partg,  g_partg);

    constexpr int S = 4;
    const size_t smA      = (size_t)S * 64 * 20 * 4;                 // 20480
    const size_t sm_kn32  = smA + (size_t)S * 16 * 36 * 4;           // 29696
    const size_t sm_nk32  = smA + (size_t)S * 32 * 20 * 4;           // 30720
    const size_t sm_kn64  = smA + (size_t)S * 16 * 68 * 4;           // 37888

    cudaFuncSetAttribute(gemm_pipe<32, S, false>, cudaFuncAttributeMaxDynamicSharedMemorySize, (int)sm_kn32);
    cudaFuncSetAttribute(gemm_pipe<32, S, true>,  cudaFuncAttributeMaxDynamicSharedMemorySize, (int)sm_nk32);
    cudaFuncSetAttribute(gemm_pipe<64, S, false>, cudaFuncAttributeMaxDynamicSharedMemorySize, (int)sm_kn64);

    k_gather<<<BB, 256>>>(idx, emb);

    // q partials = h_prev @ query_w  (BN=32, split-K 8 -> 256 blocks)
    gemm_pipe<32, S, false><<<dim3(HH / 32, 8), 256, sm_kn32>>>(
        h_prev, h_prev, HH, HH, query_w, query_w, HH, HH, p_partq, HH, HH);
    k_qbias<<<dim3(BB, 4), 256>>>(query_b);

    // qk partials = q @ key_w^T  (BN=32, split-K 8 -> 512 blocks)
    gemm_pipe<32, S, true><<<dim3((2 * HH) / 32, 8), 256, sm_nk32>>>(
        p_q, p_q, HH, HH, key_w, key_w, HH, HH, p_partqk, 2 * HH, 2 * HH);
    // scores (sums 8 qk parts) -> softmax -> weighted enc sum
    k_scores<<<dim3(BB, 5), 256>>>(enc);
    k_softmax<<<BB, 32>>>(out_attn);
    k_wenc<<<dim3(BB, 8), 256>>>(enc);

    // cprev partials = wenc @ value_w  (BN=32, split-K 8 -> 256 blocks)
    gemm_pipe<32, S, false><<<dim3(HH / 32, 8), 256, sm_kn32>>>(
        p_wenc, p_wenc, 2 * HH, 2 * HH, value_w, value_w, HH, HH, p_partc, HH, HH);
    // gates partials = [x | h_prev] @ [w_x ; w_h]  (BN=32, split-K 8 -> 1024 blocks)
    gemm_pipe<32, S, false><<<dim3((4 * HH) / 32, 8), 256, sm_kn32>>>(
        p_x, h_prev, HH, 2 * HH, w_x, w_h, 4 * HH, 4 * HH, p_partg, 4 * HH, 4 * HH);
    k_lstm<<<dim3(BB, 4), 256>>>(value_b, b_x, b_h, out_h);

    // logits = h_next @ out_w  (BN=64 -> 786 blocks; odd-ldb cp4 path)
    gemm_pipe<64, S, false><<<dim3((VV + 63) / 64, 1), 256, sm_kn64>>>(
        p_hnext, p_hnext, HH, HH, out_w, out_w, VV, VV, out_logp, VV, VV);
    k_lsm1<<<dim3(BB, 8), 256>>>(out_logp, out_b);
    k_lsm2<<<dim3(BB, 8), 256>>>(out_logp, out_b);
}

// round 10
// speedup vs baseline: 1.0137x; 1.0137x over previous
#include <cuda_runtime.h>
#include <mma.h>
#include <math.h>

using namespace nvcuda;

#define BB 64
#define LL 50
#define HH 1024
#define VV 50257

// ------------------------ scratch ------------------------
__device__ __align__(16) float g_x[BB * HH];
__device__ __align__(16) float g_q[BB * HH];
__device__ __align__(16) float g_scores[BB * LL];
__device__ __align__(16) float g_attn[BB * LL];
__device__ __align__(16) float g_wenc[BB * 2 * HH];
__device__ __align__(16) float g_hnext[BB * HH];
__device__ __align__(16) float g_lse[BB * 8 * 2];
// split-K partials (8 splits)
__device__ __align__(16) float g_partq[8 * BB * HH];
__device__ __align__(16) float g_partqk[8 * BB * 2 * HH];
__device__ __align__(16) float g_partc[8 * BB * HH];
__device__ __align__(16) float g_partg[8 * BB * 4 * HH];

// ------------------------ cp.async helpers ------------------------
__device__ __forceinline__ unsigned smem_u32(const void* p) {
    return (unsigned)__cvta_generic_to_shared(p);
}
__device__ __forceinline__ void cp16(unsigned dst, const void* src) {
    asm volatile("cp.async.cg.shared.global [%0], [%1], 16;\n" :: "r"(dst), "l"(src));
}
__device__ __forceinline__ void cp4(unsigned dst, const void* src, int sz) {
    asm volatile("cp.async.ca.shared.global [%0], [%1], 4, %2;\n" :: "r"(dst), "l"(src), "r"(sz));
}
__device__ __forceinline__ void cp_commit() { asm volatile("cp.async.commit_group;\n"); }
template <int N> __device__ __forceinline__ void cp_wait() {
    asm volatile("cp.async.wait_group %0;\n" :: "n"(N));
}

// ------------------------ embedding gather ------------------------
__global__ void __launch_bounds__(256) k_gather(const int* __restrict__ idx,
                                                const float* __restrict__ emb) {
    int b = blockIdx.x;
    const float4* src = (const float4*)(emb + (size_t)idx[b] * HH);
    float4* dst = (float4*)(g_x + b * HH);
    if (threadIdx.x < HH / 4) dst[threadIdx.x] = src[threadIdx.x];
}

// ------------------------ q = sum(8 parts) + bias ------------------------
__global__ void __launch_bounds__(256) k_qbias(const float* __restrict__ query_b) {
    int b = blockIdx.x;
    int j = blockIdx.y * 256 + threadIdx.x;
    float s = query_b[j];
#pragma unroll
    for (int p = 0; p < 8; p++) s += g_partq[p * BB * HH + b * HH + j];
    g_q[b * HH + j] = s;
}

// ------------------------ pipelined M=64 tf32 GEMM with split-K ------------------------
// C[64,N] = [A1 | A2] @ [B1 ; B2].  !B_NK: B row-major [K,N]; B_NK: B is [N,K] (B^T mult).
// gridDim.y = KS splits; split ky writes partials to C + ky*64*ldc.
// B fills: 16B cp.async when ldb % 4 == 0, else coalesced 4B cp.async (odd-ldb out_w).
// Single barrier per chunk: wait -> sync -> issue(t+S-1) -> compute.
template <int BN, int S, bool B_NK>
__global__ void __launch_bounds__(256) gemm_pipe(
    const float* __restrict__ A1, const float* __restrict__ A2, int K1, int Ktot,
    const float* __restrict__ B1, const float* __restrict__ B2, int ldb1, int ldb2,
    float* __restrict__ C, int ldc, int N) {
    constexpr int BK  = 16;
    constexpr int AP  = 20;
    constexpr int BPL = BN + 4;     // KN row stride
    constexpr int BNS = 20;         // NK row stride
    constexpr int BSTG = B_NK ? (BN * BNS) : (BK * BPL);
    constexpr int TN = BN / 32;

    extern __shared__ char dsm[];
    float* sA = (float*)dsm;
    float* sB = (float*)(dsm + (size_t)S * 64 * AP * 4);

    const int tid = threadIdx.x, w = tid >> 5;
    const int wm = w & 3, wn = w >> 2;
    const int n0 = blockIdx.x * BN;
    const int Tall = Ktot / BK;
    const int Tper = Tall / gridDim.y;
    const int t0 = blockIdx.y * Tper;
    const bool fullN = (n0 + BN) <= N;
    const bool bAligned = (((ldb1 | ldb2) & 3) == 0);
    C += (size_t)blockIdx.y * 64 * ldc;

    auto issue = [&](int t) {
        int k0 = t * BK;
        const float* Aseg; const float* Bseg; int lda, ldb, kk;
        if (k0 < K1) { Aseg = A1; Bseg = B1; lda = K1;        ldb = ldb1; kk = k0; }
        else         { Aseg = A2; Bseg = B2; lda = Ktot - K1; ldb = ldb2; kk = k0 - K1; }
        int buf = (t - t0) % S;
        // A: 64x16 floats = 256 float4, one per thread (16B-aligned sources)
        int ar = tid >> 2, av = (tid & 3) * 4;
        cp16(smem_u32(&sA[buf * 64 * AP + ar * AP + av]), Aseg + (size_t)ar * lda + kk + av);
        float* sBb = &sB[buf * BSTG];
        if (!B_NK) {
            if (bAligned) {
                constexpr int NV = BN / 4;
                constexpr int TOT = BK * NV;
#pragma unroll
                for (int i = tid; i < TOT; i += 256) {
                    int r = i / NV, c = (i % NV) * 4;
                    cp16(smem_u32(&sBb[r * BPL + c]), Bseg + (size_t)(kk + r) * ldb + n0 + c);
                }
            } else {
                // odd ldb (out_w): coalesced 4B cp.async, zfill out-of-range
                constexpr int TOT = BK * BN;
#pragma unroll
                for (int i = tid; i < TOT; i += 256) {
                    int r = i / BN, c = i % BN;
                    int n = n0 + c;
                    int ok = (fullN || n < N);
                    const float* src = Bseg + (size_t)(kk + r) * ldb + (ok ? n : 0);
                    cp4(smem_u32(&sBb[r * BPL + c]), src, ok ? 4 : 0);
                }
            }
        } else {
            constexpr int TOT = BN * 4;                // BN rows x 4 float4
#pragma unroll
            for (int i = tid; i < TOT; i += 256) {
                int r = i >> 2, c = (i & 3) * 4;
                int n = n0 + r;
                cp16(smem_u32(&sBb[r * BNS + c]), Bseg + (size_t)n * ldb + kk + c);
            }
        }
    };

    wmma::fragment<wmma::matrix_a, 16, 16, 8, wmma::precision::tf32, wmma::row_major> fa;
    wmma::fragment<wmma::accumulator, 16, 16, 8, float> fc[TN];
#pragma unroll
    for (int t = 0; t < TN; t++) wmma::fill_fragment(fc[t], 0.f);

#pragma unroll
    for (int p = 0; p < S - 1; p++) { if (p < Tper) issue(t0 + p); cp_commit(); }

    for (int t = t0; t < t0 + Tper; t++) {
        cp_wait<S - 2>();
        __syncthreads();                    // all warps done with buf (t-1)%S; chunk t resident
        if (t + S - 1 < t0 + Tper) issue(t + S - 1);
        cp_commit();
        int buf = (t - t0) % S;
        float* sAb = &sA[buf * 64 * AP];
        float* sBb = &sB[buf * BSTG];
#pragma unroll
        for (int ks = 0; ks < 2; ks++) {
            wmma::load_matrix_sync(fa, &sAb[wm * 16 * AP + ks * 8], AP);
#pragma unroll
            for (int i = 0; i < fa.num_elements; i++) fa.x[i] = wmma::__float_to_tf32(fa.x[i]);
#pragma unroll
            for (int tt = 0; tt < TN; tt++) {
                int ns = wn * (BN / 2) + tt * 16;
                if (!B_NK) {
                    wmma::fragment<wmma::matrix_b, 16, 16, 8, wmma::precision::tf32, wmma::row_major> fb;
                    wmma::load_matrix_sync(fb, &sBb[ks * 8 * BPL + ns], BPL);
#pragma unroll
                    for (int i = 0; i < fb.num_elements; i++) fb.x[i] = wmma::__float_to_tf32(fb.x[i]);
                    wmma::mma_sync(fc[tt], fa, fb, fc[tt]);
                } else {
                    wmma::fragment<wmma::matrix_b, 16, 16, 8, wmma::precision::tf32, wmma::col_major> fb;
                    wmma::load_matrix_sync(fb, &sBb[ns * BNS + ks * 8], BNS);
#pragma unroll
                    for (int i = 0; i < fb.num_elements; i++) fb.x[i] = wmma::__float_to_tf32(fb.x[i]);
                    wmma::mma_sync(fc[tt], fa, fb, fc[tt]);
                }
            }
        }
    }

    __syncthreads();
    const bool ldc_ok = (ldc & 3) == 0;
    if (ldc_ok && fullN) {
#pragma unroll
        for (int tt = 0; tt < TN; tt++) {
            int nc = n0 + wn * (BN / 2) + tt * 16;
            wmma::store_matrix_sync(&C[(size_t)(wm * 16) * ldc + nc], fc[tt], ldc, wmma::mem_row_major);
        }
    } else {
        constexpr int CP = BN + 4;
        float* sC = sA;   // spans into sB region; both dead by now
#pragma unroll
        for (int tt = 0; tt < TN; tt++) {
            int ns = wn * (BN / 2) + tt * 16;
            wmma::store_matrix_sync(&sC[(size_t)(wm * 16) * CP + ns], fc[tt], CP, wmma::mem_row_major);
        }
        __syncthreads();
        for (int i = tid; i < 64 * BN; i += 256) {
            int r = i / BN, c = i % BN;
            int n = n0 + c;
            if (n < N) C[(size_t)r * ldc + n] = sC[r * CP + c];
        }
    }
}

// ------------------------ attention scores ------------------------
__global__ void __launch_bounds__(256) k_scores(const float* __restrict__ enc) {
    int b = blockIdx.x;
    int tid = threadIdx.x, w = tid >> 5, lane = tid & 31;
    __shared__ __align__(16) float sq[2 * HH];
    for (int j = tid; j < 2 * HH; j += 256) {
        float s = 0.f;
#pragma unroll
        for (int p = 0; p < 8; p++) s += g_partqk[p * BB * 2 * HH + b * 2 * HH + j];
        sq[j] = s;
    }
    __syncthreads();

    for (int ll = w; ll < 10; ll += 8) {
        int l = blockIdx.y * 10 + ll;
        const float* e = enc + ((size_t)b * LL + l) * 2 * HH;
        float acc = 0.f;
        for (int j = lane * 4; j < 2 * HH; j += 128) {
            float4 ev = *(const float4*)(e + j);
            float4 qv = *(const float4*)(sq + j);
            acc += ev.x * qv.x + ev.y * qv.y + ev.z * qv.z + ev.w * qv.w;
        }
#pragma unroll
        for (int o = 16; o > 0; o >>= 1) acc += __shfl_xor_sync(0xffffffffu, acc, o);
        if (lane == 0) g_scores[b * LL + l] = acc * (1.f / HH);
    }
}

// ------------------------ softmax over L=50 ------------------------
__global__ void __launch_bounds__(32) k_softmax(float* __restrict__ out_attn) {
    int b = blockIdx.x, t = threadIdx.x;
    float v0 = (t < LL) ? g_scores[b * LL + t] : -1e30f;
    float v1 = (t + 32 < LL) ? g_scores[b * LL + t + 32] : -1e30f;
    float m = fmaxf(v0, v1);
#pragma unroll
    for (int o = 16; o > 0; o >>= 1) m = fmaxf(m, __shfl_xor_sync(0xffffffffu, m, o));
    float e0 = (t < LL) ? expf(v0 - m) : 0.f;
    float e1 = (t + 32 < LL) ? expf(v1 - m) : 0.f;
    float s = e0 + e1;
#pragma unroll
    for (int o = 16; o > 0; o >>= 1) s += __shfl_xor_sync(0xffffffffu, s, o);
    float inv = 1.f / s;
    if (t < LL)      { g_attn[b * LL + t] = e0 * inv;      if (out_attn) out_attn[b * LL + t] = e0 * inv; }
    if (t + 32 < LL) { g_attn[b * LL + t + 32] = e1 * inv; if (out_attn) out_attn[b * LL + t + 32] = e1 * inv; }
}

// ------------------------ weighted encoder sum (float4) ------------------------
__global__ void __launch_bounds__(256) k_wenc(const float* __restrict__ enc) {
    int b = blockIdx.x;
    int j = (blockIdx.y * 256 + threadIdx.x) * 4;     // grid.y = 2 covers 2048
    __shared__ float at[LL];
    if (threadIdx.x < LL) at[threadIdx.x] = g_attn[b * LL + threadIdx.x];
    __syncthreads();
    const float* e = enc + (size_t)b * LL * 2 * HH + j;
    float4 acc = make_float4(0.f, 0.f, 0.f, 0.f);
#pragma unroll 5
    for (int l = 0; l < LL; l++) {
        float a = at[l];
        float4 ev = *(const float4*)(e + (size_t)l * 2 * HH);
        acc.x += a * ev.x; acc.y += a * ev.y; acc.z += a * ev.z; acc.w += a * ev.w;
    }
    *(float4*)(g_wenc + b * 2 * HH + j) = acc;
}

// ------------------------ LSTM elementwise (sums 8 split-K parts, folds biases) ------------------------
__global__ void __launch_bounds__(256) k_lstm(const float* __restrict__ value_b,
                                              const float* __restrict__ b_x,
                                              const float* __restrict__ b_h,
                                              float* __restrict__ out_h) {
    int b = blockIdx.x;
    int h = blockIdx.y * 256 + threadIdx.x;
    float gf = b_x[h]          + b_h[h];
    float gi = b_x[HH + h]     + b_h[HH + h];
    float gc = b_x[2 * HH + h] + b_h[2 * HH + h];
    float go = b_x[3 * HH + h] + b_h[3 * HH + h];
#pragma unroll
    for (int p = 0; p < 8; p++) {
        const float* g = g_partg + (size_t)p * BB * 4 * HH + b * 4 * HH;
        gf += g[h]; gi += g[HH + h]; gc += g[2 * HH + h]; go += g[3 * HH + h];
    }
    float cp = value_b[h];
#pragma unroll
    for (int p = 0; p < 8; p++) cp += g_partc[p * BB * HH + b * HH + h];

    float f  = 1.f / (1.f + expf(-gf));
    float ig = 1.f / (1.f + expf(-gi));
    float cb = tanhf(gc);
    float o  = 1.f / (1.f + expf(-go));
    float c  = f * cp + ig * cb;
    float hn = o * tanhf(c);
    g_hnext[b * HH + h] = hn;
    if (out_h) out_h[b * HH + h] = hn;
}

// ------------------------ log-softmax: pass1 partial, pass2 apply (4x ILP) ------------------------
#define LSM_CH 6283
__global__ void __launch_bounds__(256) k_lsm1(const float* __restrict__ logits,
                                              const float* __restrict__ out_b) {
    int b = blockIdx.x, c = blockIdx.y, tid = threadIdx.x;
    int start = c * LSM_CH, end = min(start + LSM_CH, VV);
    const float* row = logits + (size_t)b * VV;
    __shared__ float red[256];
    float m = -1e30f;
    for (int v = start + tid * 4; v < end; v += 1024) {
#pragma unroll
        for (int u = 0; u < 4; u++) {
            int vv = v + u;
            if (vv < end) m = fmaxf(m, row[vv] + out_b[vv]);
        }
    }
    red[tid] = m; __syncthreads();
    for (int s = 128; s > 0; s >>= 1) { if (tid < s) red[tid] = fmaxf(red[tid], red[tid + s]); __syncthreads(); }
    m = red[0]; __syncthreads();
    float sum = 0.f;
    for (int v = start + tid * 4; v < end; v += 1024) {
#pragma unroll
        for (int u = 0; u < 4; u++) {
            int vv = v + u;
            if (vv < end) sum += __expf(row[vv] + out_b[vv] - m);
        }
    }
    red[tid] = sum; __syncthreads();
    for (int s = 128; s > 0; s >>= 1) { if (tid < s) red[tid] += red[tid + s]; __syncthreads(); }
    if (tid == 0) { g_lse[(b * 8 + c) * 2] = m; g_lse[(b * 8 + c) * 2 + 1] = red[0]; }
}

__global__ void __launch_bounds__(256) k_lsm2(float* __restrict__ logits,
                                              const float* __restrict__ out_b) {
    int b = blockIdx.x, c = blockIdx.y, tid = threadIdx.x;
    float M = -1e30f;
#pragma unroll
    for (int i = 0; i < 8; i++) M = fmaxf(M, g_lse[(b * 8 + i) * 2]);
    float S = 0.f;
#pragma unroll
    for (int i = 0; i < 8; i++) S += g_lse[(b * 8 + i) * 2 + 1] * __expf(g_lse[(b * 8 + i) * 2] - M);
    float lse = M + logf(S);
    int start = c * LSM_CH, end = min(start + LSM_CH, VV);
    float* row = logits + (size_t)b * VV;
    for (int v = start + tid * 4; v < end; v += 1024) {
#pragma unroll
        for (int u = 0; u < 4; u++) {
            int vv = v + u;
            if (vv < end) row[vv] = row[vv] + out_b[vv] - lse;
        }
    }
}

// ------------------------ launch ------------------------
extern "C" void kernel_launch(void* const* d_in, const int* in_sizes, int n_in,
                              void* d_out, int out_size) {
    (void)in_sizes; (void)n_in;
    const int*   idx     = (const int*)  d_in[0];
    const float* h_prev  = (const float*)d_in[1];
    const float* enc     = (const float*)d_in[2];
    const float* emb     = (const float*)d_in[3];
    const float* w_x     = (const float*)d_in[4];
    const float* b_x     = (const float*)d_in[5];
    const float* w_h     = (const float*)d_in[6];
    const float* b_h     = (const float*)d_in[7];
    const float* key_w   = (const float*)d_in[8];
    const float* value_w = (const float*)d_in[10];
    const float* value_b = (const float*)d_in[11];
    const float* query_w = (const float*)d_in[12];
    const float* query_b = (const float*)d_in[13];
    const float* out_w   = (const float*)d_in[14];
    const float* out_b   = (const float*)d_in[15];
    // d_in[9] = key_b: dropped — softmax is shift-invariant in the constant q·key_b.

    float* out      = (float*)d_out;
    float* out_logp = out;
    float* out_h    = nullptr;
    float* out_attn = nullptr;
    long long need = (long long)BB * VV + (long long)BB * HH + (long long)BB * LL;
    if ((long long)out_size >= need) {
        out_h    = out + (size_t)BB * VV;
        out_attn = out_h + (size_t)BB * HH;
    }

    float *p_x, *p_q, *p_wenc, *p_hnext, *p_partq, *p_partqk, *p_partc, *p_partg;
    cudaGetSymbolAddress((void**)&p_x,      g_x);
    cudaGetSymbolAddress((void**)&p_q,      g_q);
    cudaGetSymbolAddress((void**)&p_wenc,   g_wenc);
    cudaGetSymbolAddress((void**)&p_hnext,  g_hnext);
    cudaGetSymbolAddress((void**)&p_partq,  g_partq);
    cudaGetSymbolAddress((void**)&p_partqk, g_partqk);
    cudaGetSymbolAddress((void**)&p_partc,  g_partc);
    cudaGetSymbolAddress((void**)&p_partg,  g_partg);

    constexpr int SS = 6;   // small GEMMs: deep pipeline
    constexpr int SL = 4;   // logits GEMM
    const size_t sm_kn64_s6 = (size_t)SS * 64 * 20 * 4 + (size_t)SS * 16 * 68 * 4;   // 56832
    const size_t sm_nk64_s6 = (size_t)SS * 64 * 20 * 4 + (size_t)SS * 64 * 20 * 4;   // 61440
    const size_t sm_kn128_s4 = (size_t)SL * 64 * 20 * 4 + (size_t)SL * 16 * 132 * 4; // 54272

    cudaFuncSetAttribute(gemm_pipe<64, SS, false>,  cudaFuncAttributeMaxDynamicSharedMemorySize, (int)sm_kn64_s6);
    cudaFuncSetAttribute(gemm_pipe<64, SS, true>,   cudaFuncAttributeMaxDynamicSharedMemorySize, (int)sm_nk64_s6);
    cudaFuncSetAttribute(gemm_pipe<128, SL, false>, cudaFuncAttributeMaxDynamicSharedMemorySize, (int)sm_kn128_s4);

    k_gather<<<BB, 256>>>(idx, emb);

    // q partials = h_prev @ query_w  (BN=64, KS=8 -> 128 blocks, S=6)
    gemm_pipe<64, SS, false><<<dim3(HH / 64, 8), 256, sm_kn64_s6>>>(
        h_prev, h_prev, HH, HH, query_w, query_w, HH, HH, p_partq, HH, HH);
    k_qbias<<<dim3(BB, 4), 256>>>(query_b);

    // qk partials = q @ key_w^T  (BN=64, KS=8 -> 256 blocks, S=6)
    gemm_pipe<64, SS, true><<<dim3((2 * HH) / 64, 8), 256, sm_nk64_s6>>>(
        p_q, p_q, HH, HH, key_w, key_w, HH, HH, p_partqk, 2 * HH, 2 * HH);
    // scores (sums 8 qk parts) -> softmax -> weighted enc sum
    k_scores<<<dim3(BB, 5), 256>>>(enc);
    k_softmax<<<BB, 32>>>(out_attn);
    k_wenc<<<dim3(BB, 2), 256>>>(enc);

    // cprev partials = wenc @ value_w  (BN=64, KS=8 -> 128 blocks, S=6)
    gemm_pipe<64, SS, false><<<dim3(HH / 64, 8), 256, sm_kn64_s6>>>(
        p_wenc, p_wenc, 2 * HH, 2 * HH, value_w, value_w, HH, HH, p_partc, HH, HH);
    // gates partials = [x | h_prev] @ [w_x ; w_h]  (BN=64, KS=8 -> 512 blocks, S=6)
    gemm_pipe<64, SS, false><<<dim3((4 * HH) / 64, 8), 256, sm_kn64_s6>>>(
        p_x, h_prev, HH, 2 * HH, w_x, w_h, 4 * HH, 4 * HH, p_partg, 4 * HH, 4 * HH);
    k_lstm<<<dim3(BB, 4), 256>>>(value_b, b_x, b_h, out_h);

    // logits = h_next @ out_w  (BN=128 -> 393 blocks, S=4; odd-ldb cp4 path)
    gemm_pipe<128, SL, false><<<dim3((VV + 127) / 128, 1), 256, sm_kn128_s4>>>(
        p_hnext, p_hnext, HH, HH, out_w, out_w, VV, VV, out_logp, VV, VV);
    k_lsm1<<<dim3(BB, 8), 256>>>(out_logp, out_b);
    k_lsm2<<<dim3(BB, 8), 256>>>(out_logp, out_b);
}

// round 13
// speedup vs baseline: 1.0312x; 1.0173x over previous
#include <cuda_runtime.h>
#include <mma.h>
#include <math.h>

using namespace nvcuda;

#define BB 64
#define LL 50
#define HH 1024
#define VV 50257

// ------------------------ scratch ------------------------
__device__ __align__(16) float g_x[BB * HH];
__device__ __align__(16) float g_q[BB * HH];
__device__ __align__(16) float g_scores[BB * LL];
__device__ __align__(16) float g_attn[BB * LL];
__device__ __align__(16) float g_wenc[BB * 2 * HH];
__device__ __align__(16) float g_hnext[BB * HH];
__device__ __align__(16) float g_lse[BB * 8 * 2];
// split-K partials (8 splits)
__device__ __align__(16) float g_partq[8 * BB * HH];
__device__ __align__(16) float g_partqk[8 * BB * 2 * HH];
__device__ __align__(16) float g_partc[8 * BB * HH];
__device__ __align__(16) float g_partg[8 * BB * 4 * HH];

// ------------------------ cp.async helpers ------------------------
__device__ __forceinline__ unsigned smem_u32(const void* p) {
    return (unsigned)__cvta_generic_to_shared(p);
}
__device__ __forceinline__ void cp16(unsigned dst, const void* src) {
    asm volatile("cp.async.cg.shared.global [%0], [%1], 16;\n" :: "r"(dst), "l"(src));
}
__device__ __forceinline__ void cp4(unsigned dst, const void* src, int sz) {
    asm volatile("cp.async.ca.shared.global [%0], [%1], 4, %2;\n" :: "r"(dst), "l"(src), "r"(sz));
}
__device__ __forceinline__ void cp_commit() { asm volatile("cp.async.commit_group;\n"); }
template <int N> __device__ __forceinline__ void cp_wait() {
    asm volatile("cp.async.wait_group %0;\n" :: "n"(N));
}

// ------------------------ embedding gather ------------------------
__global__ void __launch_bounds__(256) k_gather(const int* __restrict__ idx,
                                                const float* __restrict__ emb) {
    int b = blockIdx.x;
    const float4* src = (const float4*)(emb + (size_t)idx[b] * HH);
    float4* dst = (float4*)(g_x + b * HH);
    if (threadIdx.x < HH / 4) dst[threadIdx.x] = src[threadIdx.x];
}

// ------------------------ q = sum(8 parts) + bias ------------------------
__global__ void __launch_bounds__(256) k_qbias(const float* __restrict__ query_b) {
    int b = blockIdx.x;
    int j = blockIdx.y * 256 + threadIdx.x;
    float s = query_b[j];
#pragma unroll
    for (int p = 0; p < 8; p++) s += g_partq[p * BB * HH + b * HH + j];
    g_q[b * HH + j] = s;
}

// ------------------------ shared GEMM body ------------------------
// C[64,N] = [A1 | A2] @ [B1 ; B2].  !B_NK: B row-major [K,N]; B_NK: B is [N,K] (B^T mult).
// nky = #K splits; split ky writes partials to C + ky*64*ldc.
// B fills: 16B cp.async when ldb % 4 == 0, else coalesced 4B cp.async (odd-ldb out_w).
template <int BN, int S, bool B_NK>
__device__ __forceinline__ void gemm_body(
    const float* __restrict__ A1, const float* __restrict__ A2, int K1, int Ktot,
    const float* __restrict__ B1, const float* __restrict__ B2, int ldb1, int ldb2,
    float* __restrict__ C, int ldc, int N, int bx, int ky, int nky, char* dsm) {
    constexpr int BK  = 16;
    constexpr int AP  = 20;
    constexpr int BPL = BN + 4;     // KN row stride
    constexpr int BNS = 20;         // NK row stride
    constexpr int BSTG = B_NK ? (BN * BNS) : (BK * BPL);
    constexpr int TN = BN / 32;

    float* sA = (float*)dsm;
    float* sB = (float*)(dsm + (size_t)S * 64 * AP * 4);

    const int tid = threadIdx.x, w = tid >> 5;
    const int wm = w & 3, wn = w >> 2;
    const int n0 = bx * BN;
    const int Tall = Ktot / BK;
    const int Tper = Tall / nky;
    const int t0 = ky * Tper;
    const bool fullN = (n0 + BN) <= N;
    const bool bAligned = (((ldb1 | ldb2) & 3) == 0);
    C += (size_t)ky * 64 * ldc;

    auto issue = [&](int t) {
        int k0 = t * BK;
        const float* Aseg; const float* Bseg; int lda, ldb, kk;
        if (k0 < K1) { Aseg = A1; Bseg = B1; lda = K1;        ldb = ldb1; kk = k0; }
        else         { Aseg = A2; Bseg = B2; lda = Ktot - K1; ldb = ldb2; kk = k0 - K1; }
        int buf = (t - t0) % S;
        int ar = tid >> 2, av = (tid & 3) * 4;
        cp16(smem_u32(&sA[buf * 64 * AP + ar * AP + av]), Aseg + (size_t)ar * lda + kk + av);
        float* sBb = &sB[buf * BSTG];
        if (!B_NK) {
            if (bAligned) {
                constexpr int NV = BN / 4;
                constexpr int TOT = BK * NV;
#pragma unroll
                for (int i = tid; i < TOT; i += 256) {
                    int r = i / NV, c = (i % NV) * 4;
                    cp16(smem_u32(&sBb[r * BPL + c]), Bseg + (size_t)(kk + r) * ldb + n0 + c);
                }
            } else if (fullN) {
                // odd ldb, interior block: unconditional coalesced 4B cp.async
                constexpr int TOT = BK * BN;
#pragma unroll
                for (int i = tid; i < TOT; i += 256) {
                    int r = i / BN, c = i % BN;
                    cp4(smem_u32(&sBb[r * BPL + c]), Bseg + (size_t)(kk + r) * ldb + n0 + c, 4);
                }
            } else {
                constexpr int TOT = BK * BN;
#pragma unroll
                for (int i = tid; i < TOT; i += 256) {
                    int r = i / BN, c = i % BN;
                    int n = n0 + c;
                    int ok = n < N;
                    const float* src = Bseg + (size_t)(kk + r) * ldb + (ok ? n : 0);
                    cp4(smem_u32(&sBb[r * BPL + c]), src, ok ? 4 : 0);
                }
            }
        } else {
            constexpr int TOT = BN * 4;
#pragma unroll
            for (int i = tid; i < TOT; i += 256) {
                int r = i >> 2, c = (i & 3) * 4;
                int n = n0 + r;
                cp16(smem_u32(&sBb[r * BNS + c]), Bseg + (size_t)n * ldb + kk + c);
            }
        }
    };

    wmma::fragment<wmma::matrix_a, 16, 16, 8, wmma::precision::tf32, wmma::row_major> fa;
    wmma::fragment<wmma::accumulator, 16, 16, 8, float> fc[TN];
#pragma unroll
    for (int t = 0; t < TN; t++) wmma::fill_fragment(fc[t], 0.f);

#pragma unroll
    for (int p = 0; p < S - 1; p++) { if (p < Tper) issue(t0 + p); cp_commit(); }

    for (int t = t0; t < t0 + Tper; t++) {
        cp_wait<S - 2>();
        __syncthreads();                    // all warps done with buf (t-1)%S; chunk t resident
        if (t + S - 1 < t0 + Tper) issue(t + S - 1);
        cp_commit();
        int buf = (t - t0) % S;
        float* sAb = &sA[buf * 64 * AP];
        float* sBb = &sB[buf * BSTG];
#pragma unroll
        for (int ks = 0; ks < 2; ks++) {
            wmma::load_matrix_sync(fa, &sAb[wm * 16 * AP + ks * 8], AP);
#pragma unroll
            for (int i = 0; i < fa.num_elements; i++) fa.x[i] = wmma::__float_to_tf32(fa.x[i]);
#pragma unroll
            for (int tt = 0; tt < TN; tt++) {
                int ns = wn * (BN / 2) + tt * 16;
                if (!B_NK) {
                    wmma::fragment<wmma::matrix_b, 16, 16, 8, wmma::precision::tf32, wmma::row_major> fb;
                    wmma::load_matrix_sync(fb, &sBb[ks * 8 * BPL + ns], BPL);
#pragma unroll
                    for (int i = 0; i < fb.num_elements; i++) fb.x[i] = wmma::__float_to_tf32(fb.x[i]);
                    wmma::mma_sync(fc[tt], fa, fb, fc[tt]);
                } else {
                    wmma::fragment<wmma::matrix_b, 16, 16, 8, wmma::precision::tf32, wmma::col_major> fb;
                    wmma::load_matrix_sync(fb, &sBb[ns * BNS + ks * 8], BNS);
#pragma unroll
                    for (int i = 0; i < fb.num_elements; i++) fb.x[i] = wmma::__float_to_tf32(fb.x[i]);
                    wmma::mma_sync(fc[tt], fa, fb, fc[tt]);
                }
            }
        }
    }

    __syncthreads();
    const bool ldc_ok = (ldc & 3) == 0;
    if (ldc_ok && fullN) {
#pragma unroll
        for (int tt = 0; tt < TN; tt++) {
            int nc = n0 + wn * (BN / 2) + tt * 16;
            wmma::store_matrix_sync(&C[(size_t)(wm * 16) * ldc + nc], fc[tt], ldc, wmma::mem_row_major);
        }
    } else {
        constexpr int CP = BN + 4;
        float* sC = sA;
#pragma unroll
        for (int tt = 0; tt < TN; tt++) {
            int ns = wn * (BN / 2) + tt * 16;
            wmma::store_matrix_sync(&sC[(size_t)(wm * 16) * CP + ns], fc[tt], CP, wmma::mem_row_major);
        }
        __syncthreads();
        for (int i = tid; i < 64 * BN; i += 256) {
            int r = i / BN, c = i % BN;
            int n = n0 + c;
            if (n < N) C[(size_t)r * ldc + n] = sC[r * CP + c];
        }
    }
}

// single-job kernel
template <int BN, int S, bool B_NK>
__global__ void __launch_bounds__(256) gemm_pipe(
    const float* __restrict__ A1, const float* __restrict__ A2, int K1, int Ktot,
    const float* __restrict__ B1, const float* __restrict__ B2, int ldb1, int ldb2,
    float* __restrict__ C, int ldc, int N) {
    extern __shared__ char dsm[];
    gemm_body<BN, S, B_NK>(A1, A2, K1, Ktot, B1, B2, ldb1, ldb2, C, ldc, N,
                           blockIdx.x, blockIdx.y, gridDim.y, dsm);
}

// dual-job kernel (both KN-mode): blocks [0, bxA) -> job A, [bxA, bxA+bxB) -> job B
template <int BN, int S>
__global__ void __launch_bounds__(256) gemm_dual(
    const float* __restrict__ A1a, const float* __restrict__ A2a, int K1a, int Ktota,
    const float* __restrict__ B1a, const float* __restrict__ B2a, int ldba,
    float* __restrict__ Ca, int ldca, int Na, int bxA,
    const float* __restrict__ A1b, int Ktotb,
    const float* __restrict__ B1b, int ldbb,
    float* __restrict__ Cb, int ldcb, int Nb) {
    extern __shared__ char dsm[];
    if ((int)blockIdx.x < bxA) {
        gemm_body<BN, S, false>(A1a, A2a, K1a, Ktota, B1a, B2a, ldba, ldba,
                                Ca, ldca, Na, blockIdx.x, blockIdx.y, gridDim.y, dsm);
    } else {
        gemm_body<BN, S, false>(A1b, A1b, Ktotb, Ktotb, B1b, B1b, ldbb, ldbb,
                                Cb, ldcb, Nb, blockIdx.x - bxA, blockIdx.y, gridDim.y, dsm);
    }
}

// ------------------------ attention scores ------------------------
__global__ void __launch_bounds__(256) k_scores(const float* __restrict__ enc) {
    int b = blockIdx.x;
    int tid = threadIdx.x, w = tid >> 5, lane = tid & 31;
    __shared__ __align__(16) float sq[2 * HH];
    for (int j = tid; j < 2 * HH; j += 256) {
        float s = 0.f;
#pragma unroll
        for (int p = 0; p < 8; p++) s += g_partqk[p * BB * 2 * HH + b * 2 * HH + j];
        sq[j] = s;
    }
    __syncthreads();

    for (int ll = w; ll < 10; ll += 8) {
        int l = blockIdx.y * 10 + ll;
        const float* e = enc + ((size_t)b * LL + l) * 2 * HH;
        float acc = 0.f;
        for (int j = lane * 4; j < 2 * HH; j += 128) {
            float4 ev = *(const float4*)(e + j);
            float4 qv = *(const float4*)(sq + j);
            acc += ev.x * qv.x + ev.y * qv.y + ev.z * qv.z + ev.w * qv.w;
        }
#pragma unroll
        for (int o = 16; o > 0; o >>= 1) acc += __shfl_xor_sync(0xffffffffu, acc, o);
        if (lane == 0) g_scores[b * LL + l] = acc * (1.f / HH);
    }
}

// ------------------------ softmax over L=50 ------------------------
__global__ void __launch_bounds__(32) k_softmax(float* __restrict__ out_attn) {
    int b = blockIdx.x, t = threadIdx.x;
    float v0 = (t < LL) ? g_scores[b * LL + t] : -1e30f;
    float v1 = (t + 32 < LL) ? g_scores[b * LL + t + 32] : -1e30f;
    float m = fmaxf(v0, v1);
#pragma unroll
    for (int o = 16; o > 0; o >>= 1) m = fmaxf(m, __shfl_xor_sync(0xffffffffu, m, o));
    float e0 = (t < LL) ? expf(v0 - m) : 0.f;
    float e1 = (t + 32 < LL) ? expf(v1 - m) : 0.f;
    float s = e0 + e1;
#pragma unroll
    for (int o = 16; o > 0; o >>= 1) s += __shfl_xor_sync(0xffffffffu, s, o);
    float inv = 1.f / s;
    if (t < LL)      { g_attn[b * LL + t] = e0 * inv;      if (out_attn) out_attn[b * LL + t] = e0 * inv; }
    if (t + 32 < LL) { g_attn[b * LL + t + 32] = e1 * inv; if (out_attn) out_attn[b * LL + t + 32] = e1 * inv; }
}

// ------------------------ weighted encoder sum ------------------------
__global__ void __launch_bounds__(256) k_wenc(const float* __restrict__ enc) {
    int b = blockIdx.x;
    int j = blockIdx.y * 256 + threadIdx.x;
    __shared__ float at[LL];
    if (threadIdx.x < LL) at[threadIdx.x] = g_attn[b * LL + threadIdx.x];
    __syncthreads();
    const float* e = enc + (size_t)b * LL * 2 * HH + j;
    float acc = 0.f;
#pragma unroll 5
    for (int l = 0; l < LL; l++) acc += at[l] * e[(size_t)l * 2 * HH];
    g_wenc[b * 2 * HH + j] = acc;
}

// ------------------------ LSTM elementwise (sums 8 split-K parts, folds biases) ------------------------
__global__ void __launch_bounds__(256) k_lstm(const float* __restrict__ value_b,
                                              const float* __restrict__ b_x,
                                              const float* __restrict__ b_h,
                                              float* __restrict__ out_h) {
    int b = blockIdx.x;
    int h = blockIdx.y * 256 + threadIdx.x;
    float gf = b_x[h]          + b_h[h];
    float gi = b_x[HH + h]     + b_h[HH + h];
    float gc = b_x[2 * HH + h] + b_h[2 * HH + h];
    float go = b_x[3 * HH + h] + b_h[3 * HH + h];
#pragma unroll
    for (int p = 0; p < 8; p++) {
        const float* g = g_partg + (size_t)p * BB * 4 * HH + b * 4 * HH;
        gf += g[h]; gi += g[HH + h]; gc += g[2 * HH + h]; go += g[3 * HH + h];
    }
    float cp = value_b[h];
#pragma unroll
    for (int p = 0; p < 8; p++) cp += g_partc[p * BB * HH + b * HH + h];

    float f  = 1.f / (1.f + expf(-gf));
    float ig = 1.f / (1.f + expf(-gi));
    float cb = tanhf(gc);
    float o  = 1.f / (1.f + expf(-go));
    float c  = f * cp + ig * cb;
    float hn = o * tanhf(c);
    g_hnext[b * HH + h] = hn;
    if (out_h) out_h[b * HH + h] = hn;
}

// ------------------------ log-softmax: pass1 partial, pass2 apply ------------------------
#define LSM_CH 6283
__global__ void __launch_bounds__(256) k_lsm1(const float* __restrict__ logits,
                                              const float* __restrict__ out_b) {
    int b = blockIdx.x, c = blockIdx.y, tid = threadIdx.x;
    int start = c * LSM_CH, end = min(start + LSM_CH, VV);
    const float* row = logits + (size_t)b * VV;
    __shared__ float red[256];
    float m = -1e30f;
    for (int v = start + tid; v < end; v += 256) m = fmaxf(m, row[v] + out_b[v]);
    red[tid] = m; __syncthreads();
    for (int s = 128; s > 0; s >>= 1) { if (tid < s) red[tid] = fmaxf(red[tid], red[tid + s]); __syncthreads(); }
    m = red[0]; __syncthreads();
    float sum = 0.f;
    for (int v = start + tid; v < end; v += 256) sum += __expf(row[v] + out_b[v] - m);
    red[tid] = sum; __syncthreads();
    for (int s = 128; s > 0; s >>= 1) { if (tid < s) red[tid] += red[tid + s]; __syncthreads(); }
    if (tid == 0) { g_lse[(b * 8 + c) * 2] = m; g_lse[(b * 8 + c) * 2 + 1] = red[0]; }
}

__global__ void __launch_bounds__(256) k_lsm2(float* __restrict__ logits,
                                              const float* __restrict__ out_b) {
    int b = blockIdx.x, c = blockIdx.y, tid = threadIdx.x;
    float M = -1e30f;
#pragma unroll
    for (int i = 0; i < 8; i++) M = fmaxf(M, g_lse[(b * 8 + i) * 2]);
    float S = 0.f;
#pragma unroll
    for (int i = 0; i < 8; i++) S += g_lse[(b * 8 + i) * 2 + 1] * __expf(g_lse[(b * 8 + i) * 2] - M);
    float lse = M + logf(S);
    int start = c * LSM_CH, end = min(start + LSM_CH, VV);
    float* row = logits + (size_t)b * VV;
    for (int v = start + tid; v < end; v += 256) row[v] = row[v] + out_b[v] - lse;
}

// ------------------------ launch ------------------------
extern "C" void kernel_launch(void* const* d_in, const int* in_sizes, int n_in,
                              void* d_out, int out_size) {
    (void)in_sizes; (void)n_in;
    const int*   idx     = (const int*)  d_in[0];
    const float* h_prev  = (const float*)d_in[1];
    const float* enc     = (const float*)d_in[2];
    const float* emb     = (const float*)d_in[3];
    const float* w_x     = (const float*)d_in[4];
    const float* b_x     = (const float*)d_in[5];
    const float* w_h     = (const float*)d_in[6];
    const float* b_h     = (const float*)d_in[7];
    const float* key_w   = (const float*)d_in[8];
    const float* value_w = (const float*)d_in[10];
    const float* value_b = (const float*)d_in[11];
    const float* query_w = (const float*)d_in[12];
    const float* query_b = (const float*)d_in[13];
    const float* out_w   = (const float*)d_in[14];
    const float* out_b   = (const float*)d_in[15];
    // d_in[9] = key_b: dropped — softmax is shift-invariant in the constant q·key_b.

    float* out      = (float*)d_out;
    float* out_logp = out;
    float* out_h    = nullptr;
    float* out_attn = nullptr;
    long long need = (long long)BB * VV + (long long)BB * HH + (long long)BB * LL;
    if ((long long)out_size >= need) {
        out_h    = out + (size_t)BB * VV;
        out_attn = out_h + (size_t)BB * HH;
    }

    float *p_x, *p_q, *p_wenc, *p_hnext, *p_partq, *p_partqk, *p_partc, *p_partg;
    cudaGetSymbolAddress((void**)&p_x,      g_x);
    cudaGetSymbolAddress((void**)&p_q,      g_q);
    cudaGetSymbolAddress((void**)&p_wenc,   g_wenc);
    cudaGetSymbolAddress((void**)&p_hnext,  g_hnext);
    cudaGetSymbolAddress((void**)&p_partq,  g_partq);
    cudaGetSymbolAddress((void**)&p_partqk, g_partqk);
    cudaGetSymbolAddress((void**)&p_partc,  g_partc);
    cudaGetSymbolAddress((void**)&p_partg,  g_partg);

    constexpr int S4 = 4;
    constexpr int SL = 5;   // logits: deeper pipeline
    const size_t sm_kn64  = (size_t)S4 * 64 * 20 * 4 + (size_t)S4 * 16 * 68 * 4;   // 37888
    const size_t sm_nk64  = (size_t)S4 * 64 * 20 * 4 + (size_t)S4 * 64 * 20 * 4;   // 40960
    const size_t sm_kn128 = (size_t)SL * 64 * 20 * 4 + (size_t)SL * 16 * 132 * 4;  // 67840

    cudaFuncSetAttribute(gemm_dual<64, S4>,         cudaFuncAttributeMaxDynamicSharedMemorySize, (int)sm_kn64);
    cudaFuncSetAttribute(gemm_pipe<64, S4, false>,  cudaFuncAttributeMaxDynamicSharedMemorySize, (int)sm_kn64);
    cudaFuncSetAttribute(gemm_pipe<64, S4, true>,   cudaFuncAttributeMaxDynamicSharedMemorySize, (int)sm_nk64);
    cudaFuncSetAttribute(gemm_pipe<128, SL, false>, cudaFuncAttributeMaxDynamicSharedMemorySize, (int)sm_kn128);

    k_gather<<<BB, 256>>>(idx, emb);

    // FUSED: gates partials (blocks 0..63) + q partials (blocks 64..79), KS=8
    gemm_dual<64, S4><<<dim3(64 + 16, 8), 256, sm_kn64>>>(
        p_x, h_prev, HH, 2 * HH, w_x, w_h, 4 * HH, p_partg, 4 * HH, 4 * HH, 64,
        h_prev, HH, query_w, HH, p_partq, HH, HH);
    k_qbias<<<dim3(BB, 4), 256>>>(query_b);

    // qk partials = q @ key_w^T  (BN=64, KS=8 -> 256 blocks)
    gemm_pipe<64, S4, true><<<dim3((2 * HH) / 64, 8), 256, sm_nk64>>>(
        p_q, p_q, HH, HH, key_w, key_w, HH, HH, p_partqk, 2 * HH, 2 * HH);
    // scores (sums 8 qk parts) -> softmax -> weighted enc sum
    k_scores<<<dim3(BB, 5), 256>>>(enc);
    k_softmax<<<BB, 32>>>(out_attn);
    k_wenc<<<dim3(BB, 8), 256>>>(enc);

    // cprev partials = wenc @ value_w  (BN=64, KS=8 -> 128 blocks)
    gemm_pipe<64, S4, false><<<dim3(HH / 64, 8), 256, sm_kn64>>>(
        p_wenc, p_wenc, 2 * HH, 2 * HH, value_w, value_w, HH, HH, p_partc, HH, HH);
    k_lstm<<<dim3(BB, 4), 256>>>(value_b, b_x, b_h, out_h);

    // logits = h_next @ out_w  (BN=128 -> 393 blocks, S=5; odd-ldb cp4 fast path)
    gemm_pipe<128, SL, false><<<dim3((VV + 127) / 128, 1), 256, sm_kn128>>>(
        p_hnext, p_hnext, HH, HH, out_w, out_w, VV, VV, out_logp, VV, VV);
    k_lsm1<<<dim3(BB, 8), 256>>>(out_logp, out_b);
    k_lsm2<<<dim3(BB, 8), 256>>>(out_logp, out_b);
}